// round 1
// baseline (speedup 1.0000x reference)
#include <cuda_runtime.h>
#include <cuda_bf16.h>
#include <math.h>

#define N_NODES_C 100000
#define D_C       128
#define NPB       32     // nodes per block in GEMM phase (100000 % 32 == 0 -> 3125 blocks)
#define TPB       256

// Scratch (device globals: no allocation allowed in kernel_launch)
__device__ float g_agg[(size_t)N_NODES_C * D_C];   // 51.2 MB
__device__ float g_deg[N_NODES_C];

// ---------------------------------------------------------------------------
// Kernel 1: zero agg + deg
// grid: 12500 x 256 threads, one float4 each (3.2M float4 == N_NODES*D/4)
// ---------------------------------------------------------------------------
__global__ void zero_kernel() {
    int i = blockIdx.x * blockDim.x + threadIdx.x;
    ((float4*)g_agg)[i] = make_float4(0.f, 0.f, 0.f, 0.f);
    if (i < N_NODES_C) g_deg[i] = 0.f;
}

// ---------------------------------------------------------------------------
// Kernel 2: edge scatter. One warp per edge; lane l handles float4 l.
// features + agg both fit in L2 together -> L2-bandwidth bound.
// ---------------------------------------------------------------------------
__global__ void scatter_kernel(const float* __restrict__ feat,
                               const int*   __restrict__ src,
                               const int*   __restrict__ dst,
                               int n_edges) {
    int gw   = (blockIdx.x * blockDim.x + threadIdx.x) >> 5;
    int lane = threadIdx.x & 31;
    if (gw >= n_edges) return;

    int s = 0, d = 0;
    if (lane == 0) { s = src[gw]; d = dst[gw]; }
    s = __shfl_sync(0xffffffffu, s, 0);
    d = __shfl_sync(0xffffffffu, d, 0);

    float4 v = ((const float4*)(feat + (size_t)s * D_C))[lane];
    float* a = g_agg + (size_t)d * D_C + lane * 4;
    atomicAdd(a + 0, v.x);
    atomicAdd(a + 1, v.y);
    atomicAdd(a + 2, v.z);
    atomicAdd(a + 3, v.w);
    if (lane == 0) atomicAdd(g_deg + d, 1.0f);
}

// ---------------------------------------------------------------------------
// Kernel 3: fused degree-norm + residual + GEMM (out = h @ W^T + b)
// Block: 256 threads, 32 nodes, full 128 output columns.
// Smem: Wt[128][132] (padded transpose of W), hs[32][128], bs[128], ns[32]
// Each thread: 4 nodes x 4 outs register tile; per-k: 1 LDS.128 + 4 bcast LDS
// + 16 FFMA  -> FMA-pipe bound.
// ---------------------------------------------------------------------------
#define WT_LD 132

__global__ __launch_bounds__(TPB) void gemm_kernel(const float* __restrict__ feat,
                                                   const float* __restrict__ W,
                                                   const float* __restrict__ b,
                                                   float* __restrict__ out) {
    extern __shared__ float sm[];
    float* Wt = sm;                       // 128*132
    float* hs = Wt + D_C * WT_LD;         // 32*128
    float* bs = hs + NPB * D_C;           // 128
    float* ns = bs + D_C;                 // 32

    const int tid  = threadIdx.x;
    const int base = blockIdx.x * NPB;

    // Load W (coalesced) into transposed padded smem: Wt[k][o] = W[o][k]
    #pragma unroll
    for (int idx = tid; idx < D_C * D_C; idx += TPB) {
        int o = idx >> 7;
        int k = idx & 127;
        Wt[k * WT_LD + o] = W[idx];
    }
    if (tid < D_C) bs[tid] = b[tid];
    if (tid < NPB) {
        float deg = g_deg[base + tid];
        ns[tid] = rsqrtf(fmaxf(deg, 1.0f));
    }
    __syncthreads();

    // Build h tile: hs[n][k] = (agg + feat) * norm[n]   (conflict-free STS)
    #pragma unroll
    for (int idx = tid; idx < NPB * D_C; idx += TPB) {
        int n = idx >> 7;
        size_t gi = (size_t)(base + n) * D_C + (idx & 127);
        hs[idx] = (g_agg[gi] + feat[gi]) * ns[n];
    }
    __syncthreads();

    const int o0 = (tid & 31) * 4;   // output columns (lane-contiguous float4)
    const int n0 = (tid >> 5) * 4;   // nodes (uniform within warp -> bcast LDS)

    float acc[4][4];
    #pragma unroll
    for (int i = 0; i < 4; i++)
        #pragma unroll
        for (int j = 0; j < 4; j++) acc[i][j] = 0.f;

    #pragma unroll 4
    for (int k = 0; k < D_C; k++) {
        float4 w4 = *(const float4*)(Wt + k * WT_LD + o0);
        float h0 = hs[(n0 + 0) * D_C + k];
        float h1 = hs[(n0 + 1) * D_C + k];
        float h2 = hs[(n0 + 2) * D_C + k];
        float h3 = hs[(n0 + 3) * D_C + k];
        acc[0][0] = fmaf(h0, w4.x, acc[0][0]);
        acc[0][1] = fmaf(h0, w4.y, acc[0][1]);
        acc[0][2] = fmaf(h0, w4.z, acc[0][2]);
        acc[0][3] = fmaf(h0, w4.w, acc[0][3]);
        acc[1][0] = fmaf(h1, w4.x, acc[1][0]);
        acc[1][1] = fmaf(h1, w4.y, acc[1][1]);
        acc[1][2] = fmaf(h1, w4.z, acc[1][2]);
        acc[1][3] = fmaf(h1, w4.w, acc[1][3]);
        acc[2][0] = fmaf(h2, w4.x, acc[2][0]);
        acc[2][1] = fmaf(h2, w4.y, acc[2][1]);
        acc[2][2] = fmaf(h2, w4.z, acc[2][2]);
        acc[2][3] = fmaf(h2, w4.w, acc[2][3]);
        acc[3][0] = fmaf(h3, w4.x, acc[3][0]);
        acc[3][1] = fmaf(h3, w4.y, acc[3][1]);
        acc[3][2] = fmaf(h3, w4.z, acc[3][2]);
        acc[3][3] = fmaf(h3, w4.w, acc[3][3]);
    }

    float4 bv = *(const float4*)(bs + o0);
    #pragma unroll
    for (int i = 0; i < 4; i++) {
        float4 r;
        r.x = acc[i][0] + bv.x;
        r.y = acc[i][1] + bv.y;
        r.z = acc[i][2] + bv.z;
        r.w = acc[i][3] + bv.w;
        *(float4*)(out + (size_t)(base + n0 + i) * D_C + o0) = r;
    }
}

// ---------------------------------------------------------------------------
// kernel_launch
// ---------------------------------------------------------------------------
extern "C" void kernel_launch(void* const* d_in, const int* in_sizes, int n_in,
                              void* d_out, int out_size) {
    const float* feat = (const float*)d_in[0];   // [100000,128] f32
    const int*   src  = (const int*)d_in[1];     // [600000] i32
    const int*   dst  = (const int*)d_in[2];     // [600000] i32
    const float* W    = (const float*)d_in[3];   // [128,128] f32
    const float* b    = (const float*)d_in[4];   // [128] f32
    float*       out  = (float*)d_out;

    const int n_edges = in_sizes[1];

    // allow >48KB dynamic smem for the GEMM kernel
    static const size_t smem_bytes =
        (size_t)(D_C * WT_LD + NPB * D_C + D_C + NPB) * sizeof(float);
    cudaFuncSetAttribute(gemm_kernel,
                         cudaFuncAttributeMaxDynamicSharedMemorySize,
                         (int)smem_bytes);

    // 1) zero scratch
    zero_kernel<<<(N_NODES_C * D_C / 4 + TPB - 1) / TPB, TPB>>>();

    // 2) edge scatter: one warp per edge
    int warps_needed = n_edges;
    int blocks = (warps_needed * 32 + TPB - 1) / TPB;
    scatter_kernel<<<blocks, TPB>>>(feat, src, dst, n_edges);

    // 3) fused norm + GEMM
    gemm_kernel<<<N_NODES_C / NPB, TPB, smem_bytes>>>(feat, W, b, out);
}

// round 3
// speedup vs baseline: 1.8762x; 1.8762x over previous
#include <cuda_runtime.h>
#include <cuda_bf16.h>
#include <math.h>
#include <stdint.h>

#define N_NODES_C 100000
#define D_C       128
#define TPB       256
#define TILE_M    128
#define GEMM_GRID ((N_NODES_C + TILE_M - 1) / TILE_M)   // 782

#define RS        136                      // smem row stride in bf16 (272B = 17*16B, conflict-free ldmatrix)
#define TILE_HALF (TILE_M * RS)            // bf16 elements per tile (one of hi/lo)
#define TILE_BYTES_SM (TILE_HALF * 2)      // 34816 B

// Scratch (no allocation allowed in kernel_launch)
__device__ float g_agg[(size_t)N_NODES_C * D_C];   // 51.2 MB
__device__ float g_deg[N_NODES_C];

__device__ __forceinline__ uint32_t smem_u32(const void* p) {
    uint32_t a;
    asm("{ .reg .u64 t; cvta.to.shared.u64 t, %1; cvt.u32.u64 %0, t; }" : "=r"(a) : "l"(p));
    return a;
}

// ---------------------------------------------------------------------------
// Kernel 1: zero agg + deg
// ---------------------------------------------------------------------------
__global__ void zero_kernel() {
    int i = blockIdx.x * blockDim.x + threadIdx.x;
    ((float4*)g_agg)[i] = make_float4(0.f, 0.f, 0.f, 0.f);
    if (i < N_NODES_C) g_deg[i] = 0.f;
}

// ---------------------------------------------------------------------------
// Kernel 2: edge scatter, warp/edge, vectorized red.global.add.v4.f32
// ---------------------------------------------------------------------------
__global__ void scatter_kernel(const float* __restrict__ feat,
                               const int*   __restrict__ src,
                               const int*   __restrict__ dst,
                               int n_edges) {
    int gw   = (blockIdx.x * blockDim.x + threadIdx.x) >> 5;
    int lane = threadIdx.x & 31;
    if (gw >= n_edges) return;

    int s = 0, d = 0;
    if (lane == 0) { s = __ldg(src + gw); d = __ldg(dst + gw); }
    s = __shfl_sync(0xffffffffu, s, 0);
    d = __shfl_sync(0xffffffffu, d, 0);

    float4 v = ((const float4*)(feat + (size_t)s * D_C))[lane];
    float* a = g_agg + (size_t)d * D_C + lane * 4;
    asm volatile("red.global.add.v4.f32 [%0], {%1, %2, %3, %4};"
                 :: "l"(a), "f"(v.x), "f"(v.y), "f"(v.z), "f"(v.w) : "memory");
    if (lane == 0) atomicAdd(g_deg + d, 1.0f);
}

// ---------------------------------------------------------------------------
// Kernel 3: fused norm + residual + GEMM via mma.sync (bf16 2-term split)
//   out[m][n] = sum_k h[m][k]*W[n][k] + b[n],  h=(agg+feat)*rsqrt(max(deg,1))
//   3 HMMA products: Ahi*Bhi + Alo*Bhi + Ahi*Blo
//   Block: 128 nodes x 128 outs, 256 thr = 8 warps (4M x 2N), warp tile 32x64.
// ---------------------------------------------------------------------------
__device__ __forceinline__ void ldsm_x4(uint32_t addr, uint32_t& r0, uint32_t& r1,
                                        uint32_t& r2, uint32_t& r3) {
    asm volatile("ldmatrix.sync.aligned.m8n8.x4.shared.b16 {%0,%1,%2,%3}, [%4];"
                 : "=r"(r0), "=r"(r1), "=r"(r2), "=r"(r3) : "r"(addr));
}
__device__ __forceinline__ void mma16816(float& c0, float& c1, float& c2, float& c3,
                                         uint32_t a0, uint32_t a1, uint32_t a2, uint32_t a3,
                                         uint32_t b0, uint32_t b1) {
    asm volatile("mma.sync.aligned.m16n8k16.row.col.f32.bf16.bf16.f32 "
                 "{%0,%1,%2,%3}, {%4,%5,%6,%7}, {%8,%9}, {%0,%1,%2,%3};"
                 : "+f"(c0), "+f"(c1), "+f"(c2), "+f"(c3)
                 : "r"(a0), "r"(a1), "r"(a2), "r"(a3), "r"(b0), "r"(b1));
}

// pack (v0,v1) -> bf16x2 hi and lo-residual
__device__ __forceinline__ void split2(float v0, float v1, uint32_t& hi, uint32_t& lo) {
    __nv_bfloat162 h2 = __floats2bfloat162_rn(v0, v1);
    float r0 = v0 - __bfloat162float(h2.x);
    float r1 = v1 - __bfloat162float(h2.y);
    __nv_bfloat162 l2 = __floats2bfloat162_rn(r0, r1);
    hi = *(uint32_t*)&h2;
    lo = *(uint32_t*)&l2;
}

__global__ __launch_bounds__(TPB, 1) void gemm_kernel(const float* __restrict__ feat,
                                                      const float* __restrict__ W,
                                                      const float* __restrict__ b,
                                                      float* __restrict__ out) {
    extern __shared__ __align__(16) __nv_bfloat16 sm[];
    __nv_bfloat16* Ahi = sm;
    __nv_bfloat16* Alo = Ahi + TILE_HALF;
    __nv_bfloat16* Bhi = Alo + TILE_HALF;
    __nv_bfloat16* Blo = Bhi + TILE_HALF;
    __shared__ float bs[D_C];
    __shared__ float ns[TILE_M];

    const int tid  = threadIdx.x;
    const int wid  = tid >> 5;
    const int lane = tid & 31;
    const int base = blockIdx.x * TILE_M;

    if (tid < D_C) bs[tid] = b[tid];
    if (tid < TILE_M) {
        int node = base + tid;
        float deg = (node < N_NODES_C) ? g_deg[node] : 1.0f;
        ns[tid] = rsqrtf(fmaxf(deg, 1.0f));
    }
    __syncthreads();

    // Fill A (h split) and B (W split): 2048 8-float groups each
    #pragma unroll
    for (int it = 0; it < 8; ++it) {
        int idx = tid + it * TPB;          // 0..2047
        int row = idx >> 4;                // 0..127
        int kc  = (idx & 15) << 3;         // k base (8 elems)
        int so  = row * RS + kc;           // smem element offset

        // ---- A ----
        {
            float v[8];
            int node = base + row;
            if (node < N_NODES_C) {
                const float4* fp = (const float4*)(feat + (size_t)node * D_C + kc);
                const float4* gp = (const float4*)(g_agg + (size_t)node * D_C + kc);
                float4 f0 = fp[0], f1 = fp[1];
                float4 a0 = gp[0], a1 = gp[1];
                float nrm = ns[row];
                v[0] = (f0.x + a0.x) * nrm;  v[1] = (f0.y + a0.y) * nrm;
                v[2] = (f0.z + a0.z) * nrm;  v[3] = (f0.w + a0.w) * nrm;
                v[4] = (f1.x + a1.x) * nrm;  v[5] = (f1.y + a1.y) * nrm;
                v[6] = (f1.z + a1.z) * nrm;  v[7] = (f1.w + a1.w) * nrm;
            } else {
                #pragma unroll
                for (int j = 0; j < 8; j++) v[j] = 0.f;
            }
            uint32_t hi[4], lo[4];
            #pragma unroll
            for (int j = 0; j < 4; j++) split2(v[2*j], v[2*j+1], hi[j], lo[j]);
            *(uint4*)(Ahi + so) = make_uint4(hi[0], hi[1], hi[2], hi[3]);
            *(uint4*)(Alo + so) = make_uint4(lo[0], lo[1], lo[2], lo[3]);
        }
        // ---- B ----
        {
            const float4* wp = (const float4*)(W + (size_t)row * D_C + kc);
            float4 w0 = wp[0], w1 = wp[1];
            float v[8] = {w0.x, w0.y, w0.z, w0.w, w1.x, w1.y, w1.z, w1.w};
            uint32_t hi[4], lo[4];
            #pragma unroll
            for (int j = 0; j < 4; j++) split2(v[2*j], v[2*j+1], hi[j], lo[j]);
            *(uint4*)(Bhi + so) = make_uint4(hi[0], hi[1], hi[2], hi[3]);
            *(uint4*)(Blo + so) = make_uint4(lo[0], lo[1], lo[2], lo[3]);
        }
    }
    __syncthreads();

    // Warp tiling: 4 (M) x 2 (N)
    const int m0 = (wid & 3) * 32;
    const int n0 = (wid >> 2) * 64;

    float acc[2][8][4];
    #pragma unroll
    for (int f = 0; f < 2; f++)
        #pragma unroll
        for (int nb = 0; nb < 8; nb++)
            #pragma unroll
            for (int j = 0; j < 4; j++) acc[f][nb][j] = 0.f;

    // ldmatrix base addresses (element offsets *2 bytes)
    // A (x4): row = m0 + f*16 + (lane&15), khalf = (lane>>4)*8
    uint32_t aBase[2];
    #pragma unroll
    for (int f = 0; f < 2; f++)
        aBase[f] = smem_u32(Ahi) +
                   (uint32_t)(((m0 + f * 16 + (lane & 15)) * RS + ((lane >> 4) << 3)) * 2);
    // B (x4, covers n-blocks 2p..2p+1): row = n0 + 16p + (lane&7) + (lane>>4)*8,
    //                                   khalf = ((lane>>3)&1)*8
    uint32_t bBase[4];
    #pragma unroll
    for (int p = 0; p < 4; p++)
        bBase[p] = smem_u32(Bhi) +
                   (uint32_t)(((n0 + 16 * p + (lane & 7) + ((lane >> 4) << 3)) * RS +
                               (((lane >> 3) & 1) << 3)) * 2);

    const uint32_t A_LO_D = (uint32_t)TILE_BYTES_SM;          // Ahi -> Alo delta
    const uint32_t B_LO_D = (uint32_t)TILE_BYTES_SM;          // Bhi -> Blo delta

    // products: (dA, dB): (0,0)=hi*hi, (A_LO_D,0)=lo*hi, (0,B_LO_D)=hi*lo
    #pragma unroll
    for (int prod = 0; prod < 3; prod++) {
        uint32_t dA = (prod == 1) ? A_LO_D : 0u;
        uint32_t dB = (prod == 2) ? B_LO_D : 0u;
        #pragma unroll
        for (int kk = 0; kk < 8; kk++) {
            uint32_t koff = (uint32_t)(kk * 16 * 2);   // 16 bf16 per step
            uint32_t a[2][4];
            #pragma unroll
            for (int f = 0; f < 2; f++)
                ldsm_x4(aBase[f] + dA + koff, a[f][0], a[f][1], a[f][2], a[f][3]);
            #pragma unroll
            for (int p = 0; p < 4; p++) {
                uint32_t b0, b1, b2, b3;
                ldsm_x4(bBase[p] + dB + koff, b0, b1, b2, b3);
                #pragma unroll
                for (int f = 0; f < 2; f++) {
                    mma16816(acc[f][2*p  ][0], acc[f][2*p  ][1], acc[f][2*p  ][2], acc[f][2*p  ][3],
                             a[f][0], a[f][1], a[f][2], a[f][3], b0, b1);
                    mma16816(acc[f][2*p+1][0], acc[f][2*p+1][1], acc[f][2*p+1][2], acc[f][2*p+1][3],
                             a[f][0], a[f][1], a[f][2], a[f][3], b2, b3);
                }
            }
        }
    }

    // Epilogue: D frag -> out.  c0,c1: row=lane/4, cols=(lane%4)*2+{0,1}; c2,c3: row+8
    const int qr = lane >> 2;
    const int qc = (lane & 3) * 2;
    #pragma unroll
    for (int f = 0; f < 2; f++) {
        int m_lo = m0 + f * 16 + qr;
        int m_hi = m_lo + 8;
        int node_lo = base + m_lo;
        int node_hi = base + m_hi;
        #pragma unroll
        for (int nb = 0; nb < 8; nb++) {
            int col = n0 + nb * 8 + qc;
            float b0v = bs[col], b1v = bs[col + 1];
            if (node_lo < N_NODES_C) {
                float2 o = make_float2(acc[f][nb][0] + b0v, acc[f][nb][1] + b1v);
                *(float2*)(out + (size_t)node_lo * D_C + col) = o;
            }
            if (node_hi < N_NODES_C) {
                float2 o = make_float2(acc[f][nb][2] + b0v, acc[f][nb][3] + b1v);
                *(float2*)(out + (size_t)node_hi * D_C + col) = o;
            }
        }
    }
}

// ---------------------------------------------------------------------------
// kernel_launch
// ---------------------------------------------------------------------------
extern "C" void kernel_launch(void* const* d_in, const int* in_sizes, int n_in,
                              void* d_out, int out_size) {
    const float* feat = (const float*)d_in[0];   // [100000,128] f32
    const int*   src  = (const int*)d_in[1];     // [600000] i32
    const int*   dst  = (const int*)d_in[2];     // [600000] i32
    const float* W    = (const float*)d_in[3];   // [128,128] f32
    const float* b    = (const float*)d_in[4];   // [128] f32
    float*       out  = (float*)d_out;

    const int n_edges = in_sizes[1];

    const int smem_bytes = 4 * TILE_BYTES_SM;    // 139264 B dynamic
    cudaFuncSetAttribute(gemm_kernel,
                         cudaFuncAttributeMaxDynamicSharedMemorySize, smem_bytes);

    // 1) zero scratch
    zero_kernel<<<(N_NODES_C * D_C / 4) / TPB, TPB>>>();

    // 2) edge scatter (warp per edge, v4 reductions)
    int blocks = (n_edges * 32 + TPB - 1) / TPB;
    scatter_kernel<<<blocks, TPB>>>(feat, src, dst, n_edges);

    // 3) fused norm + residual + HMMA GEMM
    gemm_kernel<<<GEMM_GRID, TPB, smem_bytes>>>(feat, W, b, out);
}